// round 17
// baseline (speedup 1.0000x reference)
#include <cuda_runtime.h>
#include <cuda_fp16.h>
#include <cstdint>

#define HW 4096
#define NB 8

// ---------------- device scratch (channel-major [b][c][p]) ----------------
__device__ uint32_t g_wh[262144];   // packed fp16 hi weights, [j][c/2], K-major
__device__ uint32_t g_wl[262144];   // packed fp16 lo (residual)
#define OWQ 0
#define OWK 65536
#define OWV 98304
#define OWO 131072
#define OWE 163840
#define OWC 229376
__device__ float g_Sq[256], g_Tq[256];
__device__ float g_Sk[256], g_Tk[256];
__device__ float g_Sv[256], g_Tv[256];
__device__ float g_fs[256], g_fb[256];
__device__ float g_rf[NB * HW], g_af[NB * HW];
__device__ float g_rg[NB * HW], g_ag[NB * HW];
__device__ float g_q   [NB * 256 * HW];
__device__ float g_k   [NB * 256 * HW];
__device__ float g_v   [NB * 256 * HW];
__device__ float g_a   [NB * 256 * HW];
__device__ float g_cin [NB * 256 * HW];
__device__ float g_comb[NB * 256 * HW];
__device__ float g_efp [NB * 256 * HW];
__device__ float g_kp[NB * 16 * 256];
__device__ float g_vp[NB * 16 * 256];

// ---------------- helpers ----------------
__device__ __forceinline__ uint32_t pack_hi(float x0, float x1, float& r0, float& r1) {
    __half h0 = __float2half_rn(x0), h1 = __float2half_rn(x1);
    r0 = x0 - __half2float(h0);
    r1 = x1 - __half2float(h1);
    return (uint32_t)__half_as_ushort(h0) | ((uint32_t)__half_as_ushort(h1) << 16);
}
__device__ __forceinline__ uint32_t pack2(float x0, float x1) {
    __half h0 = __float2half_rn(x0), h1 = __float2half_rn(x1);
    return (uint32_t)__half_as_ushort(h0) | ((uint32_t)__half_as_ushort(h1) << 16);
}
__device__ __forceinline__ void mma16(float* c, const uint32_t* a, const uint32_t* b) {
    asm volatile(
        "mma.sync.aligned.m16n8k16.row.col.f32.f16.f16.f32 "
        "{%0,%1,%2,%3}, {%4,%5,%6,%7}, {%8,%9}, {%0,%1,%2,%3};"
        : "+f"(c[0]), "+f"(c[1]), "+f"(c[2]), "+f"(c[3])
        : "r"(a[0]), "r"(a[1]), "r"(a[2]), "r"(a[3]), "r"(b[0]), "r"(b[1]));
}

// ---------------- prep: split+pack all weights (hi/lo fp16) ----------------
__global__ void fold_kernel(const float* __restrict__ wq, const float* __restrict__ gf,
                            const float* __restrict__ wk, const float* __restrict__ wv,
                            const float* __restrict__ gg, const float* __restrict__ wo,
                            const float* __restrict__ efp_w, const float* __restrict__ outc_w)
{
    int idx = blockIdx.x * 256 + threadIdx.x;   // 0..262143
    float x0, x1;
    if (idx < 65536) {                                    // wq folded, transpose -> [j][c]
        int j = idx >> 8, c = (idx & 255) * 2;
        x0 = wq[c * 256 + j] * gf[c];
        x1 = wq[(c + 1) * 256 + j] * gf[c + 1];
    } else if (idx < 98304) {                             // wk folded
        int r = idx - 65536, j = r >> 7, c = (r & 127) * 2;
        x0 = wk[c * 256 + j] * gg[c];
        x1 = wk[(c + 1) * 256 + j] * gg[c + 1];
    } else if (idx < 131072) {                            // wv folded
        int r = idx - 98304, j = r >> 7, c = (r & 127) * 2;
        x0 = wv[c * 256 + j] * gg[c];
        x1 = wv[(c + 1) * 256 + j] * gg[c + 1];
    } else if (idx < 163840) {                            // wo transpose
        int r = idx - 131072, j = r >> 7, c = (r & 127) * 2;
        x0 = wo[c * 256 + j];
        x1 = wo[(c + 1) * 256 + j];
    } else if (idx < 229376) {                            // efp_w direct [j][c]
        int r = idx - 163840, j = r >> 8, c = (r & 255) * 2;
        x0 = efp_w[j * 512 + c];
        x1 = efp_w[j * 512 + c + 1];
    } else {                                              // outc_w direct
        int r = idx - 229376, j = r >> 7, c = (r & 127) * 2;
        x0 = outc_w[j * 256 + c];
        x1 = outc_w[j * 256 + c + 1];
    }
    float r0, r1;
    g_wh[idx] = pack_hi(x0, x1, r0, r1);
    g_wl[idx] = pack2(r0, r1);
}

// ---------------- vec: parallel block reductions --------------------------
__global__ __launch_bounds__(128)
void vec_kernel(const float* __restrict__ wq, const float* __restrict__ bq,
                const float* __restrict__ gf, const float* __restrict__ bf,
                const float* __restrict__ wk, const float* __restrict__ bk,
                const float* __restrict__ wv, const float* __restrict__ bv,
                const float* __restrict__ gg, const float* __restrict__ bg,
                const float* __restrict__ outc_b,
                const float* __restrict__ bn_g, const float* __restrict__ bn_b,
                const float* __restrict__ bn_m, const float* __restrict__ bn_v)
{
    int kind = blockIdx.x >> 8, j = blockIdx.x & 255;
    int t = threadIdx.x;
    if (kind == 3) {
        if (t == 0) {
            float sc = bn_g[j] * rsqrtf(bn_v[j] + 1e-5f);
            g_fs[j] = sc;
            g_fb[j] = (outc_b[j] - bn_m[j]) * sc + bn_b[j];
        }
        return;
    }
    __shared__ float sS[128], sT[128];
    const float* w; const float* g; const float* bb; int C;
    if (kind == 0)      { w = wq; g = gf; bb = bf; C = 512; }
    else if (kind == 1) { w = wk; g = gg; bb = bg; C = 256; }
    else                { w = wv; g = gg; bb = bg; C = 256; }
    float S = 0.f, T = 0.f;
    for (int c = t; c < C; c += 128) {
        float wv_ = w[c * 256 + j];
        S = fmaf(wv_, g[c], S); T = fmaf(wv_, bb[c], T);
    }
    sS[t] = S; sT[t] = T;
    __syncthreads();
    for (int off = 64; off; off >>= 1) {
        if (t < off) { sS[t] += sS[t + off]; sT[t] += sT[t + off]; }
        __syncthreads();
    }
    if (t == 0) {
        if (kind == 0)      { g_Sq[j] = sS[0]; g_Tq[j] = sT[0] + bq[j]; }
        else if (kind == 1) { g_Sk[j] = sS[0]; g_Tk[j] = sT[0] + bk[j]; }
        else                { g_Sv[j] = sS[0]; g_Tv[j] = sT[0] + bv[j]; }
    }
}

// ---------------- per-pixel LN stats (split-C, 2x occupancy) --------------
template <int WHICH>
__global__ __launch_bounds__(256)
void stats_kernel(const float* __restrict__ X)
{
    constexpr int C = (WHICH == 0) ? 512 : 256;
    __shared__ float ss[256], ss2[256];
    int px = threadIdx.x & 127, hf = threadIdx.x >> 7;
    int gid = blockIdx.x * 128 + px;
    const float* base = X + (size_t)(gid >> 12) * C * HW + (gid & (HW - 1))
                      + (size_t)(hf * (C / 2)) * HW;
    float s = 0.f, s2 = 0.f;
#pragma unroll 8
    for (int c = 0; c < C / 2; c++) {
        float v = base[(size_t)c * HW];
        s += v; s2 = fmaf(v, v, s2);
    }
    ss[threadIdx.x] = s; ss2[threadIdx.x] = s2;
    __syncthreads();
    if (hf == 0) {
        s  = ss[px]  + ss[px + 128];
        s2 = ss2[px] + ss2[px + 128];
        const float invC = 1.0f / (float)C;
        float m = s * invC;
        float var = fmaf(-m, m, s2 * invC);
        float r = rsqrtf(var + 1e-5f);
        if (WHICH == 0) { g_rf[gid] = r; g_af[gid] = -r * m; }
        else            { g_rg[gid] = r; g_ag[gid] = -r * m; }
    }
}

// ---------------- mma.sync fp16 2-term GEMM (channel-major) ----------------
// D[j][p] = sum_c W[j][c]*X[c][p], W = Wh+Wl pre-split, X single fp16 round.
// CTA 128j x 128p, warp 32j x 64p, K-chunk 32, double-buffered.
// Per 8192-u32 buffer: A interleaved (hi,lo) pairs @0, row stride 40 u32;
// B @5120, row stride 24 u32, slot-permuted so b-frag words are adjacent.
// All fragment loads are LDS.64, bank-conflict-free.
#define SMEM_TOT 67584   // epilogue buf 128*132*4 dominates (staging = 64KB)

template <int CFG>
__global__ __launch_bounds__(256)
void gemm_tc(const float* __restrict__ Xext, const float* __restrict__ Bias,
             float* __restrict__ Cext)
{
    constexpr int K    = (CFG == 0 || CFG == 4) ? 512 : 256;
    constexpr int NCH  = K / 32;
    constexpr int WOFS = (CFG == 0) ? OWQ : (CFG == 1) ? OWK : (CFG == 2) ? OWV
                       : (CFG == 3) ? OWO : (CFG == 4) ? OWE : OWC;
    extern __shared__ char smem[];
    uint32_t* S32 = (uint32_t*)smem;
    const int tid = threadIdx.x, wid = tid >> 5, lane = tid & 31;
    const int lq = lane & 3, lr = lane >> 2;
    const int m0w = (wid >> 1) * 32;    // warp j offset
    const int n0w = (wid & 1) * 64;     // warp p offset
    const int b  = blockIdx.z;
    const int P0 = blockIdx.x * 128;
    const int J0 = blockIdx.y * 128;

    const float* X = (CFG == 3) ? g_cin : (CFG == 5) ? g_efp : Xext;
    const float* Xb = X + (size_t)b * K * HW;

    // B staging: thread covers c-pair (tid&15), 8 pixels (tid>>4)
    const int cpair = tid & 15, pg = tid >> 4;
    const int bslot = (cpair >> 3) * 8 + (cpair & 3) * 2 + ((cpair >> 2) & 1);
    const float* xs0 = Xb + (size_t)(2 * cpair) * HW + P0 + pg * 8;
    // A staging: thread covers weight row (tid>>1), half (tid&1)
    const int jrow = tid >> 1, half = tid & 1;
    const uint4* wh4 = (const uint4*)(g_wh + WOFS + (size_t)(J0 + jrow) * (K >> 1)) + half * 2;
    const uint4* wl4 = (const uint4*)(g_wl + WOFS + (size_t)(J0 + jrow) * (K >> 1)) + half * 2;

    float acc[2][8][4];
#pragma unroll
    for (int i = 0; i < 2; i++)
#pragma unroll
        for (int j = 0; j < 8; j++)
#pragma unroll
            for (int k = 0; k < 4; k++) acc[i][j][k] = 0.f;

    float4 xb4[4];          // [0,1]=even-c 8p, [2,3]=odd-c 8p
    uint4 whr[2], wlr[2];

#define LOADCH(ch) { \
    const float* s0 = xs0 + (size_t)(ch) * 32 * HW; \
    xb4[0] = *(const float4*)(s0);           xb4[1] = *(const float4*)(s0 + 4); \
    xb4[2] = *(const float4*)(s0 + HW);      xb4[3] = *(const float4*)(s0 + HW + 4); \
    whr[0] = wh4[(ch) * 4]; whr[1] = wh4[(ch) * 4 + 1]; \
    wlr[0] = wl4[(ch) * 4]; wlr[1] = wl4[(ch) * 4 + 1]; }

#define STORECH(nb) { \
    uint32_t* B0 = S32 + (nb) * 8192; \
    uint32_t* Ai = B0; \
    uint32_t* Bp = B0 + 5120; \
    uint4* dA = (uint4*)(Ai + jrow * 40 + half * 16); \
    dA[0] = make_uint4(whr[0].x, wlr[0].x, whr[0].y, wlr[0].y); \
    dA[1] = make_uint4(whr[0].z, wlr[0].z, whr[0].w, wlr[0].w); \
    dA[2] = make_uint4(whr[1].x, wlr[1].x, whr[1].y, wlr[1].y); \
    dA[3] = make_uint4(whr[1].z, wlr[1].z, whr[1].w, wlr[1].w); \
    const float* pe = (const float*)&xb4[0]; \
    const float* po = (const float*)&xb4[2]; \
_Pragma("unroll") \
    for (int i = 0; i < 8; i++) { \
        Bp[(pg * 8 + i) * 24 + bslot] = pack2(pe[i], po[i]); \
    } }

    LOADCH(0);
    STORECH(0);
    __syncthreads();

    for (int ch = 0; ch < NCH; ch++) {
        if (ch + 1 < NCH) LOADCH(ch + 1);
        uint32_t* B0 = S32 + (ch & 1) * 8192;
        uint32_t* Ai = B0;
        uint32_t* Bp = B0 + 5120;
#pragma unroll
        for (int ks = 0; ks < 2; ks++) {
            uint32_t ah[2][4], al[2][4];
            const int cidx = (ks * 8 + lq) * 2;
#pragma unroll
            for (int mt = 0; mt < 2; mt++) {
                const int rbase = m0w + mt * 16;
                uint2 t0 = *(const uint2*)(Ai + (rbase + lr) * 40 + cidx);
                uint2 t1 = *(const uint2*)(Ai + (rbase + lr + 8) * 40 + cidx);
                uint2 t2 = *(const uint2*)(Ai + (rbase + lr) * 40 + cidx + 8);
                uint2 t3 = *(const uint2*)(Ai + (rbase + lr + 8) * 40 + cidx + 8);
                ah[mt][0] = t0.x; ah[mt][1] = t1.x; ah[mt][2] = t2.x; ah[mt][3] = t3.x;
                al[mt][0] = t0.y; al[mt][1] = t1.y; al[mt][2] = t2.y; al[mt][3] = t3.y;
            }
#pragma unroll
            for (int g = 0; g < 4; g++) {
#pragma unroll
                for (int sub = 0; sub < 2; sub++) {
                    int o = (n0w + g * 16 + sub * 8 + lr) * 24 + ks * 8 + lq * 2;
                    uint2 bb = *(const uint2*)(Bp + o);
                    uint32_t b2[2] = { bb.x, bb.y };
#pragma unroll
                    for (int mt = 0; mt < 2; mt++) {
                        float* a = acc[mt][g * 2 + sub];
                        mma16(a, ah[mt], b2);
                        mma16(a, al[mt], b2);
                    }
                }
            }
        }
        if (ch + 1 < NCH) STORECH((ch + 1) & 1);
        __syncthreads();
    }
#undef LOADCH
#undef STORECH

    // ---- epilogue: stage acc [j][p] in smem, then coalesced stores ----
    float* buf = (float*)smem;   // stride 132 floats per j-row
#pragma unroll
    for (int mt = 0; mt < 2; mt++) {
#pragma unroll
        for (int nt = 0; nt < 8; nt++) {
            int ml = m0w + mt * 16 + lr;
            int nl = n0w + nt * 8 + lq * 2;
            const float* ac = acc[mt][nt];
            buf[ml * 132 + nl]           = ac[0];
            buf[ml * 132 + nl + 1]       = ac[1];
            buf[(ml + 8) * 132 + nl]     = ac[2];
            buf[(ml + 8) * 132 + nl + 1] = ac[3];
        }
    }
    __syncthreads();

    const int pcol = lane * 4;
    float4 rp = {0, 0, 0, 0}, apv = {0, 0, 0, 0};
    if (CFG <= 2) {
        const float* rv = (CFG == 0) ? g_rf : g_rg;
        const float* av = (CFG == 0) ? g_af : g_ag;
        rp  = *(const float4*)(rv + (size_t)b * HW + P0 + pcol);
        apv = *(const float4*)(av + (size_t)b * HW + P0 + pcol);
    }
    float* Cb = ((CFG == 0) ? g_q : (CFG == 1) ? g_k : (CFG == 2) ? g_v
               : (CFG == 3) ? g_comb : (CFG == 4) ? g_efp : Cext)
              + (size_t)b * 256 * HW;
#pragma unroll
    for (int it = 0; it < 16; it++) {
        int jl = it * 8 + wid;
        int j = J0 + jl;
        float4 v = *(const float4*)(buf + jl * 132 + pcol);
        float4 o;
        if (CFG <= 2) {
            const float* Sv = (CFG == 0) ? g_Sq : (CFG == 1) ? g_Sk : g_Sv;
            const float* Tv = (CFG == 0) ? g_Tq : (CFG == 1) ? g_Tk : g_Tv;
            float S = Sv[j], T = Tv[j];
            o.x = fmaf(rp.x, v.x, fmaf(apv.x, S, T));
            o.y = fmaf(rp.y, v.y, fmaf(apv.y, S, T));
            o.z = fmaf(rp.z, v.z, fmaf(apv.z, S, T));
            o.w = fmaf(rp.w, v.w, fmaf(apv.w, S, T));
        } else if (CFG == 3) {
            float bb = Bias[j];
            o.x = v.x + bb; o.y = v.y + bb; o.z = v.z + bb; o.w = v.w + bb;
        } else if (CFG == 4) {
            // gated epilogue: efp = (Wx + bias) * comb
            float bb = Bias[j];
            float4 cv = *(const float4*)(g_comb + (size_t)b * 256 * HW
                                         + (size_t)j * HW + P0 + pcol);
            o.x = (v.x + bb) * cv.x; o.y = (v.y + bb) * cv.y;
            o.z = (v.z + bb) * cv.z; o.w = (v.w + bb) * cv.w;
        } else {
            float fs = g_fs[j], fb = g_fb[j];
            o.x = fmaxf(fmaf(v.x, fs, fb), 0.f);
            o.y = fmaxf(fmaf(v.y, fs, fb), 0.f);
            o.z = fmaxf(fmaf(v.z, fs, fb), 0.f);
            o.w = fmaxf(fmaf(v.w, fs, fb), 0.f);
        }
        *(float4*)(Cb + (size_t)j * HW + P0 + pcol) = o;
    }
}

// ---------------- pool: 128 blocks (b x cell_row x chan-quarter) ----------
__global__ __launch_bounds__(256)
void pool_kernel()
{
    int bx = blockIdx.x;         // b*16 + ch*4 + dc
    int b  = bx >> 4;
    int ch = (bx >> 2) & 3;      // cell row
    int dc = bx & 3;             // channel quarter
    int d0 = threadIdx.x >> 2;
    int cw = threadIdx.x & 3;

    int d = dc * 64 + d0;
    size_t base = (size_t)(b * 256 + d) * HW + (size_t)(ch * 16) * 64 + cw * 16;
    float mx = -3.4e38f, sm = 0.f;
    for (int hh = 0; hh < 16; hh++) {
        const float4* kr = (const float4*)(g_k + base + hh * 64);
        const float4* vr = (const float4*)(g_v + base + hh * 64);
#pragma unroll
        for (int i = 0; i < 4; i++) {
            float4 kv = kr[i], vv = vr[i];
            mx = fmaxf(mx, fmaxf(fmaxf(kv.x, kv.y), fmaxf(kv.z, kv.w)));
            sm += (vv.x + vv.y) + (vv.z + vv.w);
        }
    }
    int cell = ch * 4 + cw;
    g_kp[(b * 16 + cell) * 256 + d] = mx;
    g_vp[(b * 16 + cell) * 256 + d] = sm * (1.0f / 256.0f);
}

// ---------------- pooled attention (128-thread blocks, 256 blocks) --------
__global__ __launch_bounds__(128)
void attn_kernel()
{
    __shared__ float ks[4096];
    __shared__ float vs[4096];
    int b   = blockIdx.y;
    int pix = blockIdx.x * 128 + threadIdx.x;

    for (int i = threadIdx.x; i < 4096; i += 128) {
        ks[i] = g_kp[b * 4096 + i];
        vs[i] = g_vp[b * 4096 + i];
    }
    __syncthreads();

    float s[16];
#pragma unroll
    for (int t = 0; t < 16; t++) s[t] = 0.f;

    const float* qb = g_q + (size_t)b * 256 * HW + pix;
    for (int d = 0; d < 256; d++) {
        float qd = qb[(size_t)d * HW];
#pragma unroll
        for (int t = 0; t < 16; t++)
            s[t] = fmaf(qd, ks[t * 256 + d], s[t]);
    }
    float m = -3.4e38f;
#pragma unroll
    for (int t = 0; t < 16; t++) { s[t] *= 0.0625f; m = fmaxf(m, s[t]); }
    float sum = 0.f;
#pragma unroll
    for (int t = 0; t < 16; t++) { s[t] = __expf(s[t] - m); sum += s[t]; }
    float inv = 1.0f / sum;
#pragma unroll
    for (int t = 0; t < 16; t++) s[t] *= inv;

    float* ab = g_a + (size_t)b * 256 * HW + pix;
    for (int d = 0; d < 256; d++) {
        float acc = 0.f;
#pragma unroll
        for (int t = 0; t < 16; t++)
            acc = fmaf(s[t], vs[t * 256 + d], acc);
        ab[(size_t)d * HW] = acc;
    }
}

// ---------------- depthwise 3x3 + attn add (proven R6 version) ------------
__global__ __launch_bounds__(256)
void dwadd_kernel(const float* __restrict__ dwk)
{
    int bc   = blockIdx.y;             // b*256 + c
    int c    = bc & 255;
    int pix0 = (blockIdx.x * 256 + threadIdx.x) * 4;
    int h = pix0 >> 6, w0 = pix0 & 63;

    float k0 = dwk[c * 9 + 0], k1 = dwk[c * 9 + 1], k2 = dwk[c * 9 + 2];
    float k3 = dwk[c * 9 + 3], k4 = dwk[c * 9 + 4], k5 = dwk[c * 9 + 5];
    float k6 = dwk[c * 9 + 6], k7 = dwk[c * 9 + 7], k8 = dwk[c * 9 + 8];

    const float* qc = g_q + (size_t)bc * HW;
    const float* ac = g_a + (size_t)bc * HW;
    float*       oc = g_cin + (size_t)bc * HW;

    float acc[4];
#pragma unroll
    for (int i = 0; i < 4; i++) acc[i] = ac[pix0 + i];

#pragma unroll
    for (int dy = -1; dy <= 1; dy++) {
        int hh = h + dy;
        if (hh < 0 || hh > 63) continue;
        const float* row = qc + hh * 64;
        float ka = (dy == -1) ? k0 : (dy == 0) ? k3 : k6;
        float kb = (dy == -1) ? k1 : (dy == 0) ? k4 : k7;
        float kc = (dy == -1) ? k2 : (dy == 0) ? k5 : k8;
        float x[6];
#pragma unroll
        for (int i = 0; i < 6; i++) {
            int ww = w0 - 1 + i;
            x[i] = (ww >= 0 && ww <= 63) ? row[ww] : 0.0f;
        }
#pragma unroll
        for (int i = 0; i < 4; i++) {
            acc[i] = fmaf(ka, x[i], acc[i]);
            acc[i] = fmaf(kb, x[i + 1], acc[i]);
            acc[i] = fmaf(kc, x[i + 2], acc[i]);
        }
    }
#pragma unroll
    for (int i = 0; i < 4; i++) oc[pix0 + i] = acc[i];
}

// ---------------- launch ----------------
extern "C" void kernel_launch(void* const* d_in, const int* in_sizes, int n_in,
                              void* d_out, int out_size)
{
    const float* e_f    = (const float*)d_in[0];
    const float* e_g    = (const float*)d_in[1];
    const float* ln_f_g = (const float*)d_in[4];
    const float* ln_f_b = (const float*)d_in[5];
    const float* ln_g_g = (const float*)d_in[6];
    const float* ln_g_b = (const float*)d_in[7];
    const float* wq     = (const float*)d_in[8];
    const float* bq     = (const float*)d_in[9];
    const float* wk     = (const float*)d_in[10];
    const float* bk     = (const float*)d_in[11];
    const float* wv     = (const float*)d_in[12];
    const float* bv     = (const float*)d_in[13];
    const float* wo     = (const float*)d_in[14];
    const float* bo     = (const float*)d_in[15];
    const float* dwk    = (const float*)d_in[16];
    const float* efp_w  = (const float*)d_in[17];
    const float* efp_b  = (const float*)d_in[18];
    const float* outc_w = (const float*)d_in[19];
    const float* outc_b = (const float*)d_in[20];
    const float* bn_g   = (const float*)d_in[21];
    const float* bn_b   = (const float*)d_in[22];
    const float* bn_m   = (const float*)d_in[23];
    const float* bn_v   = (const float*)d_in[24];
    float* out = (float*)d_out;

    cudaFuncSetAttribute((const void*)gemm_tc<0>, cudaFuncAttributeMaxDynamicSharedMemorySize, SMEM_TOT);
    cudaFuncSetAttribute((const void*)gemm_tc<1>, cudaFuncAttributeMaxDynamicSharedMemorySize, SMEM_TOT);
    cudaFuncSetAttribute((const void*)gemm_tc<2>, cudaFuncAttributeMaxDynamicSharedMemorySize, SMEM_TOT);
    cudaFuncSetAttribute((const void*)gemm_tc<3>, cudaFuncAttributeMaxDynamicSharedMemorySize, SMEM_TOT);
    cudaFuncSetAttribute((const void*)gemm_tc<4>, cudaFuncAttributeMaxDynamicSharedMemorySize, SMEM_TOT);
    cudaFuncSetAttribute((const void*)gemm_tc<5>, cudaFuncAttributeMaxDynamicSharedMemorySize, SMEM_TOT);

    fold_kernel<<<1024, 256>>>(wq, ln_f_g, wk, wv, ln_g_g, wo, efp_w, outc_w);
    vec_kernel<<<1024, 128>>>(wq, bq, ln_f_g, ln_f_b, wk, bk, wv, bv, ln_g_g, ln_g_b,
                              outc_b, bn_g, bn_b, bn_m, bn_v);
    stats_kernel<0><<<256, 256>>>(e_f);
    stats_kernel<1><<<256, 256>>>(e_g);

    dim3 gg(32, 2, 8);
    gemm_tc<0><<<gg, 256, SMEM_TOT>>>(e_f, nullptr, nullptr);   // Q
    gemm_tc<1><<<gg, 256, SMEM_TOT>>>(e_g, nullptr, nullptr);   // K
    gemm_tc<2><<<gg, 256, SMEM_TOT>>>(e_g, nullptr, nullptr);   // V

    pool_kernel<<<128, 256>>>();
    attn_kernel<<<dim3(32, 8), 128>>>();
    dwadd_kernel<<<dim3(4, 2048), 256>>>(dwk);

    gemm_tc<3><<<gg, 256, SMEM_TOT>>>(nullptr, bo, nullptr);    // comb = wo(cin)+bo
    gemm_tc<4><<<gg, 256, SMEM_TOT>>>(e_f, efp_b, nullptr);     // efp = (Wx+b)*comb
    gemm_tc<5><<<gg, 256, SMEM_TOT>>>(nullptr, nullptr, out);   // BN + ReLU
}